// round 14
// baseline (speedup 1.0000x reference)
#include <cuda_runtime.h>
#include <cuda_bf16.h>
#include <math.h>
#include <stdint.h>

// ---------------------------------------------------------------------------
// Problem constants
// ---------------------------------------------------------------------------
#define B_   4
#define S_   1024
#define H_   1024
#define NH_  16
#define HD_  64
#define NREL 257   // 2*128+1
#define PTS  264   // padded Pt row stride (even, >= 263)
#define MTOT (B_ * S_)   // 4096

// ---------------------------------------------------------------------------
// Scratch (device globals — no cudaMalloc allowed)
// ---------------------------------------------------------------------------
__device__ float g_V[MTOT * H_];

__device__ __nv_bfloat16 g_xh[MTOT * H_];
__device__ __nv_bfloat16 g_xl[MTOT * H_];
__device__ __nv_bfloat16 g_Wqh[H_ * H_];
__device__ __nv_bfloat16 g_Wql[H_ * H_];
__device__ __nv_bfloat16 g_Wkh[H_ * H_];
__device__ __nv_bfloat16 g_Wkl[H_ * H_];
__device__ __nv_bfloat16 g_Wvh[H_ * H_];
__device__ __nv_bfloat16 g_Wvl[H_ * H_];
__device__ __nv_bfloat16 g_Woh[H_ * H_];
__device__ __nv_bfloat16 g_Wol[H_ * H_];
__device__ __nv_bfloat16 g_ah[MTOT * H_];
__device__ __nv_bfloat16 g_al[MTOT * H_];

__device__ __nv_bfloat16 g_Qh[MTOT * H_];
__device__ __nv_bfloat16 g_Ql[MTOT * H_];
__device__ __nv_bfloat16 g_Kh[MTOT * H_];
__device__ __nv_bfloat16 g_Kl[MTOT * H_];
__device__ __nv_bfloat16 g_Vth[MTOT * H_];   // [b][head][d][s]
__device__ __nv_bfloat16 g_Vtl[MTOT * H_];
__device__ __nv_bfloat16 g_relB[NREL * HD_]; // bf16 copy of rel_emb [r][d]

// ---------------------------------------------------------------------------
// Helpers
// ---------------------------------------------------------------------------
__device__ __forceinline__ uint32_t smem_u32(const void* p) {
    uint32_t a;
    asm("{ .reg .u64 t; cvta.to.shared.u64 t, %1; cvt.u32.u64 %0, t; }"
        : "=r"(a) : "l"(p));
    return a;
}

#define CP16(dst_u32, src_ptr) \
    asm volatile("cp.async.cg.shared.global [%0], [%1], 16;" \
        :: "r"(dst_u32), "l"(src_ptr))

__device__ __forceinline__ void mma16816(float* c,
    uint32_t a0, uint32_t a1, uint32_t a2, uint32_t a3, uint32_t b0, uint32_t b1)
{
    asm volatile(
        "mma.sync.aligned.m16n8k16.row.col.f32.bf16.bf16.f32 "
        "{%0,%1,%2,%3}, {%4,%5,%6,%7}, {%8,%9}, {%0,%1,%2,%3};\n"
        : "+f"(c[0]), "+f"(c[1]), "+f"(c[2]), "+f"(c[3])
        : "r"(a0), "r"(a1), "r"(a2), "r"(a3), "r"(b0), "r"(b1));
}

__device__ __forceinline__ void ldsm_x4(uint32_t& r0, uint32_t& r1,
                                        uint32_t& r2, uint32_t& r3, uint32_t addr)
{
    asm volatile("ldmatrix.sync.aligned.m8n8.x4.shared.b16 {%0,%1,%2,%3}, [%4];"
                 : "=r"(r0), "=r"(r1), "=r"(r2), "=r"(r3) : "r"(addr));
}

// Swizzled offset, 64-byte rows (GEMM tiles); kbyte multiple of 16.
__device__ __forceinline__ uint32_t swz_u(uint32_t row, uint32_t kbyte)
{
    return row * 64 + ((((kbyte >> 4) ^ ((row >> 1) & 3)) << 4));
}
// Swizzled offset, 128-byte rows (attention tiles); kbyte multiple of 16.
__device__ __forceinline__ uint32_t swzb_u(uint32_t row, uint32_t kbyte)
{
    return row * 128 + ((((kbyte >> 4) ^ (row & 7)) << 4));
}

// Pack two fp32 into bf16x2 hi word + residual lo word.
__device__ __forceinline__ void pack_hl(float x0, float x1, uint32_t& h, uint32_t& l)
{
    asm("cvt.rn.bf16x2.f32 %0, %1, %2;" : "=r"(h) : "f"(x1), "f"(x0));
    float f0 = __uint_as_float(h << 16);
    float f1 = __uint_as_float(h & 0xffff0000u);
    float r0 = x0 - f0, r1 = x1 - f1;
    asm("cvt.rn.bf16x2.f32 %0, %1, %2;" : "=r"(l) : "f"(r1), "f"(r0));
}

__device__ __forceinline__ uint32_t pack_h(float x0, float x1)
{
    uint32_t h;
    asm("cvt.rn.bf16x2.f32 %0, %1, %2;" : "=r"(h) : "f"(x1), "f"(x0));
    return h;
}

// ---------------------------------------------------------------------------
// Fused split, 4 float4 per thread (MLP=4):
// x (1024 blk), 4 weights (256 blk each), rel (5 blk).
// ---------------------------------------------------------------------------
#define SPLIT_BLOCKS (1024 + 1024 + 5)

__global__ __launch_bounds__(256) void split_all(
    const float4* __restrict__ x,  uint2* __restrict__ xh,  uint2* __restrict__ xl,
    const float4* __restrict__ Wq, uint2* __restrict__ wqh, uint2* __restrict__ wql,
    const float4* __restrict__ Wk, uint2* __restrict__ wkh, uint2* __restrict__ wkl,
    const float4* __restrict__ Wv, uint2* __restrict__ wvh, uint2* __restrict__ wvl,
    const float4* __restrict__ Wo, uint2* __restrict__ woh, uint2* __restrict__ wol,
    const float4* __restrict__ rel4, uint2* __restrict__ relB4)
{
    const int bx = blockIdx.x;
    const int tid = threadIdx.x;

    if (bx < 2048) {
        const float4* src;
        uint2 *hi, *lo;
        int base;
        if (bx < 1024) {
            src = x; hi = xh; lo = xl;
            base = bx * 1024;
        } else {
            int wsel = (bx - 1024) >> 8;
            src = (wsel == 0) ? Wq : (wsel == 1) ? Wk : (wsel == 2) ? Wv : Wo;
            hi  = (wsel == 0) ? wqh : (wsel == 1) ? wkh : (wsel == 2) ? wvh : woh;
            lo  = (wsel == 0) ? wql : (wsel == 1) ? wkl : (wsel == 2) ? wvl : wol;
            base = ((bx - 1024) & 255) * 1024;
        }
        float4 v[4];
#pragma unroll
        for (int k = 0; k < 4; k++) v[k] = src[base + tid + k * 256];
#pragma unroll
        for (int k = 0; k < 4; k++) {
            int i = base + tid + k * 256;
            uint32_t h0, l0, h1, l1;
            pack_hl(v[k].x, v[k].y, h0, l0);
            pack_hl(v[k].z, v[k].w, h1, l1);
            hi[i] = make_uint2(h0, h1);
            lo[i] = make_uint2(l0, l1);
        }
    } else {
        int base = (bx - 2048) * 1024;
#pragma unroll
        for (int k = 0; k < 4; k++) {
            int i = base + tid + k * 256;
            if (i < (NREL * HD_ / 4)) {
                float4 v = rel4[i];
                relB4[i] = make_uint2(pack_h(v.x, v.y), pack_h(v.z, v.w));
            }
        }
    }
}

// ---------------------------------------------------------------------------
// Transpose + split V: [b,s,head*64+d] fp32 -> [b,head,d,s] bf16 hi/lo
// ---------------------------------------------------------------------------
__global__ __launch_bounds__(256) void vtrans_kernel(
    const float* __restrict__ V, __nv_bfloat16* __restrict__ Vth,
    __nv_bfloat16* __restrict__ Vtl)
{
    __shared__ float t[64][68];
    const int s0 = blockIdx.x * 64;
    const int n = blockIdx.y;
    const int b = blockIdx.z;
    const int tid = threadIdx.x;

    for (int idx = tid; idx < 1024; idx += 256) {
        int row = idx >> 4, c4 = idx & 15;
        float4 v = *(const float4*)&V[((size_t)(b * S_) + s0 + row) * H_ + n * HD_ + c4 * 4];
        *(float4*)&t[row][c4 * 4] = v;
    }
    __syncthreads();
    for (int idx = tid; idx < 1024; idx += 256) {
        int d = idx >> 4, sg = idx & 15;
        float v0 = t[sg * 4 + 0][d];
        float v1 = t[sg * 4 + 1][d];
        float v2 = t[sg * 4 + 2][d];
        float v3 = t[sg * 4 + 3][d];
        uint32_t h0, l0, h1, l1;
        pack_hl(v0, v1, h0, l0);
        pack_hl(v2, v3, h1, l1);
        size_t o = ((size_t)((b * NH_ + n) * HD_) + d) * S_ + s0 + sg * 4;
        *(uint2*)(Vth + o) = make_uint2(h0, h1);
        *(uint2*)(Vtl + o) = make_uint2(l0, l1);
    }
}

// ---------------------------------------------------------------------------
// GEMM mainloop body: cp.async double-buffered, 128x128x32 tiles, ldmatrix.
// ---------------------------------------------------------------------------
#define GEMM_SMEM 65536

__device__ __forceinline__ void gemm_core(
    const __nv_bfloat16* Ahg, const __nv_bfloat16* Alg,
    const __nv_bfloat16* Bhg, const __nv_bfloat16* Blg,
    uint8_t* gsm, uint32_t sb, int m0, int n0,
    int warp_m, int warp_n, int lane, int tid, float acc[2][8][4])
{
    auto issue = [&](int kt, int buf) {
#pragma unroll
        for (int l = 0; l < 2; l++) {
            int s2 = tid + l * 256;
            int row = s2 >> 2;
            int seg = s2 & 3;
            uint32_t soff = (uint32_t)(buf * 32768 + row * 64 + ((seg ^ ((row >> 1) & 3)) << 4));
            size_t ga = (size_t)(m0 + row) * H_ + kt * 32 + seg * 8;
            size_t gb = (size_t)(n0 + row) * H_ + kt * 32 + seg * 8;
            CP16(sb + soff,         Ahg + ga);
            CP16(sb + soff + 8192,  Alg + ga);
            CP16(sb + soff + 16384, Bhg + gb);
            CP16(sb + soff + 24576, Blg + gb);
        }
    };

    const int mmi = lane >> 3;
    const int rr = lane & 7;

    issue(0, 0);
    asm volatile("cp.async.commit_group;");

#pragma unroll 1
    for (int kt = 0; kt < 32; kt++) {
        const int cur = kt & 1;
        if (kt < 31) {
            issue(kt + 1, cur ^ 1);
            asm volatile("cp.async.commit_group;");
            asm volatile("cp.async.wait_group 1;");
        } else {
            asm volatile("cp.async.wait_group 0;");
        }
        __syncthreads();

        const uint32_t uAh = sb + cur * 32768;
        const uint32_t uAl = uAh + 8192;
        const uint32_t uBh = uAh + 16384;
        const uint32_t uBl = uAh + 24576;

#pragma unroll
        for (int kk = 0; kk < 64; kk += 32) {
            uint32_t ah[2][4], al[2][4];
#pragma unroll
            for (int mt = 0; mt < 2; mt++) {
                uint32_t arow = warp_m * 32 + mt * 16 + ((mmi & 1) << 3) + rr;
                uint32_t abyte = kk + ((mmi >> 1) << 4);
                uint32_t aoff = swz_u(arow, abyte);
                ldsm_x4(ah[mt][0], ah[mt][1], ah[mt][2], ah[mt][3], uAh + aoff);
                ldsm_x4(al[mt][0], al[mt][1], al[mt][2], al[mt][3], uAl + aoff);
            }
#pragma unroll
            for (int p = 0; p < 4; p++) {
                uint32_t brow = warp_n * 64 + 16 * p + ((mmi >> 1) << 3) + rr;
                uint32_t bbyte = kk + ((mmi & 1) << 4);
                uint32_t boff = swz_u(brow, bbyte);
                uint32_t bh0, bh1, bh2, bh3, bl0, bl1, bl2, bl3;
                ldsm_x4(bh0, bh1, bh2, bh3, uBh + boff);
                ldsm_x4(bl0, bl1, bl2, bl3, uBl + boff);
#pragma unroll
                for (int mt = 0; mt < 2; mt++) {
                    mma16816(acc[mt][2 * p], ah[mt][0], ah[mt][1], ah[mt][2], ah[mt][3], bh0, bh1);
                    mma16816(acc[mt][2 * p], ah[mt][0], ah[mt][1], ah[mt][2], ah[mt][3], bl0, bl1);
                    mma16816(acc[mt][2 * p], al[mt][0], al[mt][1], al[mt][2], al[mt][3], bh0, bh1);
                    mma16816(acc[mt][2 * p + 1], ah[mt][0], ah[mt][1], ah[mt][2], ah[mt][3], bh2, bh3);
                    mma16816(acc[mt][2 * p + 1], ah[mt][0], ah[mt][1], ah[mt][2], ah[mt][3], bl2, bl3);
                    mma16816(acc[mt][2 * p + 1], al[mt][0], al[mt][1], al[mt][2], al[mt][3], bh2, bh3);
                }
            }
        }
        __syncthreads();
    }
}

// ---------------------------------------------------------------------------
// Fused QKV GEMM (gridDim.z = 3): z=0 -> Qh/Ql, z=1 -> Kh/Kl, z=2 -> V fp32.
// ---------------------------------------------------------------------------
__global__ __launch_bounds__(256) void gemm_qkv(
    const __nv_bfloat16* __restrict__ Ahg, const __nv_bfloat16* __restrict__ Alg,
    const __nv_bfloat16* __restrict__ Wqh, const __nv_bfloat16* __restrict__ Wql,
    const float* __restrict__ bq, __nv_bfloat16* __restrict__ Qh, __nv_bfloat16* __restrict__ Ql,
    const __nv_bfloat16* __restrict__ Wkh, const __nv_bfloat16* __restrict__ Wkl,
    const float* __restrict__ bk, __nv_bfloat16* __restrict__ Kh, __nv_bfloat16* __restrict__ Kl,
    const __nv_bfloat16* __restrict__ Wvh, const __nv_bfloat16* __restrict__ Wvl,
    const float* __restrict__ bv, float* __restrict__ V)
{
    extern __shared__ __align__(16) uint8_t gsm[];
    const uint32_t sb = smem_u32(gsm);

    const int z = blockIdx.z;
    const __nv_bfloat16* Bhg = (z == 0) ? Wqh : (z == 1) ? Wkh : Wvh;
    const __nv_bfloat16* Blg = (z == 0) ? Wql : (z == 1) ? Wkl : Wvl;
    const float* bias = (z == 0) ? bq : (z == 1) ? bk : bv;

    const int tid = threadIdx.x;
    const int lane = tid & 31;
    const int wid = tid >> 5;
    const int warp_m = wid >> 1;
    const int warp_n = wid & 1;
    const int m0 = blockIdx.y * 128;
    const int n0 = blockIdx.x * 128;
    const int g = lane >> 2;
    const int t4 = lane & 3;

    float acc[2][8][4];
#pragma unroll
    for (int mt = 0; mt < 2; mt++)
#pragma unroll
        for (int nt = 0; nt < 8; nt++)
#pragma unroll
            for (int i = 0; i < 4; i++) acc[mt][nt][i] = 0.f;

    gemm_core(Ahg, Alg, Bhg, Blg, gsm, sb, m0, n0, warp_m, warp_n, lane, tid, acc);

    __nv_bfloat16* Oh = (z == 0) ? Qh : Kh;
    __nv_bfloat16* Ol = (z == 0) ? Ql : Kl;
#pragma unroll
    for (int mt = 0; mt < 2; mt++) {
        int row = m0 + warp_m * 32 + mt * 16 + g;
#pragma unroll
        for (int nt = 0; nt < 8; nt++) {
            int col = n0 + warp_n * 64 + nt * 8 + t4 * 2;
            float2 bv2 = *(const float2*)&bias[col];
            float v0 = acc[mt][nt][0] + bv2.x, v1 = acc[mt][nt][1] + bv2.y;
            float v2 = acc[mt][nt][2] + bv2.x, v3 = acc[mt][nt][3] + bv2.y;
            if (z == 2) {
                *(float2*)&V[(size_t)row * H_ + col] = make_float2(v0, v1);
                *(float2*)&V[(size_t)(row + 8) * H_ + col] = make_float2(v2, v3);
            } else {
                uint32_t h0, l0, h1, l1;
                pack_hl(v0, v1, h0, l0);
                pack_hl(v2, v3, h1, l1);
                *(uint32_t*)(Oh + (size_t)row * H_ + col) = h0;
                *(uint32_t*)(Ol + (size_t)row * H_ + col) = l0;
                *(uint32_t*)(Oh + (size_t)(row + 8) * H_ + col) = h1;
                *(uint32_t*)(Ol + (size_t)(row + 8) * H_ + col) = l1;
            }
        }
    }
}

// ---------------------------------------------------------------------------
// Final output GEMM (fp32 epilogue): out = A @ Wo^T + bo
// ---------------------------------------------------------------------------
__global__ __launch_bounds__(256) void gemm_mma(
    const __nv_bfloat16* __restrict__ Ahg, const __nv_bfloat16* __restrict__ Alg,
    const __nv_bfloat16* __restrict__ Bhg, const __nv_bfloat16* __restrict__ Blg,
    const float* __restrict__ bias, float* __restrict__ C)
{
    extern __shared__ __align__(16) uint8_t gsm[];
    const uint32_t sb = smem_u32(gsm);

    const int tid = threadIdx.x;
    const int lane = tid & 31;
    const int wid = tid >> 5;
    const int warp_m = wid >> 1;
    const int warp_n = wid & 1;
    const int m0 = blockIdx.y * 128;
    const int n0 = blockIdx.x * 128;
    const int g = lane >> 2;
    const int t4 = lane & 3;

    float acc[2][8][4];
#pragma unroll
    for (int mt = 0; mt < 2; mt++)
#pragma unroll
        for (int nt = 0; nt < 8; nt++)
#pragma unroll
            for (int i = 0; i < 4; i++) acc[mt][nt][i] = 0.f;

    gemm_core(Ahg, Alg, Bhg, Blg, gsm, sb, m0, n0, warp_m, warp_n, lane, tid, acc);

#pragma unroll
    for (int mt = 0; mt < 2; mt++) {
        int row = m0 + warp_m * 32 + mt * 16 + g;
#pragma unroll
        for (int nt = 0; nt < 8; nt++) {
            int col = n0 + warp_n * 64 + nt * 8 + t4 * 2;
            float2 bv = *(const float2*)&bias[col];
            float2 o0, o1;
            o0.x = acc[mt][nt][0] + bv.x; o0.y = acc[mt][nt][1] + bv.y;
            o1.x = acc[mt][nt][2] + bv.x; o1.y = acc[mt][nt][3] + bv.y;
            *(float2*)&C[(size_t)row * H_ + col] = o0;
            *(float2*)&C[(size_t)(row + 8) * H_ + col] = o1;
        }
    }
}

// ---------------------------------------------------------------------------
// Tensor-core flash attention, banded rel-bias.
// 128 threads / 4 warps; q-tile 64; k-tiles 64; ldmatrix frags; Pt via MMA.
// Tiles with |k0-q0| >= 192 use clamped per-row constant bias (no gather).
// smem = PtB 33792 + 2 stages x 32768 = 99328 B -> 2 CTAs/SM.
// ---------------------------------------------------------------------------
#define AAT_PT 0
#define AAT_ST 33792
#define ATTN_SMEM (33792 + 65536)

__global__ __launch_bounds__(128) void attn_mma(
    const __nv_bfloat16* __restrict__ Qh, const __nv_bfloat16* __restrict__ Ql,
    const __nv_bfloat16* __restrict__ Kh, const __nv_bfloat16* __restrict__ Kl,
    const __nv_bfloat16* __restrict__ Vth, const __nv_bfloat16* __restrict__ Vtl,
    const __nv_bfloat16* __restrict__ relB,
    __nv_bfloat16* __restrict__ Aout_h, __nv_bfloat16* __restrict__ Aout_l)
{
    extern __shared__ __align__(16) uint8_t dynsm[];
    const uint32_t sbase = smem_u32(dynsm);
    uint8_t* sQh = dynsm;              // temporary, inside PtB region
    uint8_t* sQl = dynsm + 8192;
    __nv_bfloat16* PtB = (__nv_bfloat16*)(dynsm + AAT_PT);

    const int b  = blockIdx.z;
    const int n  = blockIdx.y;
    const int q0 = blockIdx.x * 64;
    const int tid = threadIdx.x;
    const int lane = tid & 31;
    const int w = tid >> 5;
    const int g = lane >> 2;
    const int t4 = lane & 3;
    const int mmi = lane >> 3;
    const int rr = lane & 7;

    const __nv_bfloat16* Vhb = Vth + (size_t)((b * NH_ + n) * HD_) * S_;
    const __nv_bfloat16* Vlb = Vtl + (size_t)((b * NH_ + n) * HD_) * S_;

    auto issue_kv = [&](int kt, int buf) {
        const int k0 = kt * 64;
        const uint32_t st = sbase + AAT_ST + buf * 32768;
#pragma unroll
        for (int l = 0; l < 4; l++) {
            int idx = tid + l * 128;
            int row = idx >> 3, seg = idx & 7;
            uint32_t off = (uint32_t)(row * 128 + ((seg ^ (row & 7)) << 4));
            size_t gk = ((size_t)(b * S_) + k0 + row) * H_ + n * HD_ + seg * 8;
            size_t gv = (size_t)row * S_ + k0 + seg * 8;
            CP16(st + off,         Kh + gk);
            CP16(st + off + 8192,  Kl + gk);
            CP16(st + off + 16384, Vhb + gv);
            CP16(st + off + 24576, Vlb + gv);
        }
    };

    // Q tile -> smem (temporary, in PtB region)
    for (int idx = tid; idx < 512; idx += 128) {
        int row = idx >> 3, seg = idx & 7;
        uint32_t off = (uint32_t)(row * 128 + ((seg ^ (row & 7)) << 4));
        size_t gq = ((size_t)(b * S_) + q0 + row) * H_ + n * HD_ + seg * 8;
        *(uint4*)(sQh + off) = *(const uint4*)(Qh + gq);
        *(uint4*)(sQl + off) = *(const uint4*)(Ql + gq);
    }

    // Prefetch first K/V tile
    issue_kv(0, 0);
    asm volatile("cp.async.commit_group;");
    __syncthreads();

    // Resident Q A-frags
    uint32_t qah[4][4], qal[4][4];
    {
        const uint32_t uQh = sbase;
        const uint32_t uQl = sbase + 8192;
#pragma unroll
        for (int kb = 0; kb < 4; kb++) {
            uint32_t arow = 16 * w + ((mmi & 1) << 3) + rr;
            uint32_t abyte = kb * 32 + ((mmi >> 1) << 4);
            uint32_t aoff = swzb_u(arow, abyte);
            ldsm_x4(qah[kb][0], qah[kb][1], qah[kb][2], qah[kb][3], uQh + aoff);
            ldsm_x4(qal[kb][0], qal[kb][1], qal[kb][2], qal[kb][3], uQl + aoff);
        }
    }
    __syncthreads();   // Q smem dead; PtB may now overwrite it

    const int ql0 = 16 * w + g;
    const int qg0 = q0 + ql0;

    // Pt via MMA: Pt[q][r] = Qh[q] . relB[r]  (1-pass bf16, per-warp rows)
    {
#pragma unroll 4
        for (int j = 0; j < 33; j++) {
            int r = 8 * j + g;
            int rc = min(r, NREL - 1);
            const __nv_bfloat16* rb = relB + rc * HD_;
            float c[4] = {0.f, 0.f, 0.f, 0.f};
#pragma unroll
            for (int kb = 0; kb < 4; kb++) {
                uint32_t b0 = *(const uint32_t*)(rb + kb * 16 + 2 * t4);
                uint32_t b1 = *(const uint32_t*)(rb + kb * 16 + 2 * t4 + 8);
                mma16816(c, qah[kb][0], qah[kb][1], qah[kb][2], qah[kb][3], b0, b1);
            }
            int col = 8 * j + 2 * t4;
            *(uint32_t*)(PtB + ql0 * PTS + col) = pack_h(c[0], c[1]);
            *(uint32_t*)(PtB + (ql0 + 8) * PTS + col) = pack_h(c[2], c[3]);
        }
        __syncwarp();   // cross-lane smem dependency within warp
    }

    // Clamped-constant biases for far tiles (row ql0 and ql0+8)
    const float cbL0 = __bfloat162float(PtB[ql0 * PTS + 0]);
    const float cbL1 = __bfloat162float(PtB[(ql0 + 8) * PTS + 0]);
    const float cbH0 = __bfloat162float(PtB[ql0 * PTS + 256]);
    const float cbH1 = __bfloat162float(PtB[(ql0 + 8) * PTS + 256]);

    float oacc[8][4];
#pragma unroll
    for (int j = 0; j < 8; j++)
#pragma unroll
        for (int i = 0; i < 4; i++) oacc[j][i] = 0.f;
    float rmax0 = -INFINITY, rmax1 = -INFINITY;
    float rsum0 = 0.f, rsum1 = 0.f;

#pragma unroll 1
    for (int kt = 0; kt < 16; kt++) {
        const int k0 = kt * 64;
        const int cur = kt & 1;
        asm volatile("cp.async.wait_group 0;");
        __syncthreads();
        if (kt < 15) {
            issue_kv(kt + 1, cur ^ 1);
            asm volatile("cp.async.commit_group;");
        }

        const uint32_t uKh = sbase + AAT_ST + cur * 32768;
        const uint32_t uKl = uKh + 8192;
        const uint32_t uVh = uKh + 16384;
        const uint32_t uVl = uKh + 24576;

        // QK^T
        float sc[8][4];
#pragma unroll
        for (int j = 0; j < 8; j++)
#pragma unroll
            for (int i = 0; i < 4; i++) sc[j][i] = 0.f;
#pragma unroll
        for (int kb = 0; kb < 4; kb++) {
#pragma unroll
            for (int jp = 0; jp < 4; jp++) {
                uint32_t brow = 16 * jp + ((mmi >> 1) << 3) + rr;
                uint32_t bbyte = kb * 32 + ((mmi & 1) << 4);
                uint32_t boff = swzb_u(brow, bbyte);
                uint32_t bh0, bh1, bh2, bh3, bl0, bl1, bl2, bl3;
                ldsm_x4(bh0, bh1, bh2, bh3, uKh + boff);
                ldsm_x4(bl0, bl1, bl2, bl3, uKl + boff);
                mma16816(sc[2 * jp], qah[kb][0], qah[kb][1], qah[kb][2], qah[kb][3], bh0, bh1);
                mma16816(sc[2 * jp], qah[kb][0], qah[kb][1], qah[kb][2], qah[kb][3], bl0, bl1);
                mma16816(sc[2 * jp], qal[kb][0], qal[kb][1], qal[kb][2], qal[kb][3], bh0, bh1);
                mma16816(sc[2 * jp + 1], qah[kb][0], qah[kb][1], qah[kb][2], qah[kb][3], bh2, bh3);
                mma16816(sc[2 * jp + 1], qah[kb][0], qah[kb][1], qah[kb][2], qah[kb][3], bl2, bl3);
                mma16816(sc[2 * jp + 1], qal[kb][0], qal[kb][1], qal[kb][2], qal[kb][3], bh2, bh3);
            }
        }

        // Bias + scale: banded (gather) vs far (clamped constant)
        const int diff = k0 - q0;
        if (diff >= 192) {
#pragma unroll
            for (int j = 0; j < 8; j++) {
                sc[j][0] = (sc[j][0] + cbH0) * 0.125f;
                sc[j][1] = (sc[j][1] + cbH0) * 0.125f;
                sc[j][2] = (sc[j][2] + cbH1) * 0.125f;
                sc[j][3] = (sc[j][3] + cbH1) * 0.125f;
            }
        } else if (diff <= -192) {
#pragma unroll
            for (int j = 0; j < 8; j++) {
                sc[j][0] = (sc[j][0] + cbL0) * 0.125f;
                sc[j][1] = (sc[j][1] + cbL0) * 0.125f;
                sc[j][2] = (sc[j][2] + cbL1) * 0.125f;
                sc[j][3] = (sc[j][3] + cbL1) * 0.125f;
            }
        } else {
#pragma unroll
            for (int j = 0; j < 8; j++) {
                int col = k0 + 8 * j + 2 * t4;
                int r00 = min(128, max(-128, col     - qg0)) + 128;
                int r01 = min(128, max(-128, col + 1 - qg0)) + 128;
                int r10 = min(128, max(-128, col     - qg0 - 8)) + 128;
                int r11 = min(128, max(-128, col + 1 - qg0 - 8)) + 128;
                sc[j][0] = (sc[j][0] + __bfloat162float(PtB[ql0 * PTS + r00])) * 0.125f;
                sc[j][1] = (sc[j][1] + __bfloat162float(PtB[ql0 * PTS + r01])) * 0.125f;
                sc[j][2] = (sc[j][2] + __bfloat162float(PtB[(ql0 + 8) * PTS + r10])) * 0.125f;
                sc[j][3] = (sc[j][3] + __bfloat162float(PtB[(ql0 + 8) * PTS + r11])) * 0.125f;
            }
        }

        // Online softmax
        float m0 = -INFINITY, m1 = -INFINITY;
#pragma unroll
        for (int j = 0; j < 8; j++) {
            m0 = fmaxf(m0, fmaxf(sc[j][0], sc[j][1]));
            m1 = fmaxf(m1, fmaxf(sc[j][2], sc[j][3]));
        }
        m0 = fmaxf(m0, __shfl_xor_sync(0xffffffffu, m0, 1, 4));
        m0 = fmaxf(m0, __shfl_xor_sync(0xffffffffu, m0, 2, 4));
        m1 = fmaxf(m1, __shfl_xor_sync(0xffffffffu, m1, 1, 4));
        m1 = fmaxf(m1, __shfl_xor_sync(0xffffffffu, m1, 2, 4));

        float nm0 = fmaxf(rmax0, m0);
        float nm1 = fmaxf(rmax1, m1);
        float esc0 = __expf(rmax0 - nm0);
        float esc1 = __expf(rmax1 - nm1);
        rmax0 = nm0; rmax1 = nm1;

        float s0 = 0.f, s1 = 0.f;
#pragma unroll
        for (int j = 0; j < 8; j++) {
            sc[j][0] = __expf(sc[j][0] - nm0);
            sc[j][1] = __expf(sc[j][1] - nm0);
            sc[j][2] = __expf(sc[j][2] - nm1);
            sc[j][3] = __expf(sc[j][3] - nm1);
            s0 += sc[j][0] + sc[j][1];
            s1 += sc[j][2] + sc[j][3];
        }
        s0 += __shfl_xor_sync(0xffffffffu, s0, 1, 4);
        s0 += __shfl_xor_sync(0xffffffffu, s0, 2, 4);
        s1 += __shfl_xor_sync(0xffffffffu, s1, 1, 4);
        s1 += __shfl_xor_sync(0xffffffffu, s1, 2, 4);
        rsum0 = rsum0 * esc0 + s0;
        rsum1 = rsum1 * esc1 + s1;

#pragma unroll
        for (int j = 0; j < 8; j++) {
            oacc[j][0] *= esc0; oacc[j][1] *= esc0;
            oacc[j][2] *= esc1; oacc[j][3] *= esc1;
        }

        // PV
#pragma unroll
        for (int kb = 0; kb < 4; kb++) {
            uint32_t ah0, ah1, ah2, ah3, al0, al1, al2, al3;
            pack_hl(sc[2 * kb][0], sc[2 * kb][1], ah0, al0);
            pack_hl(sc[2 * kb][2], sc[2 * kb][3], ah1, al1);
            pack_hl(sc[2 * kb + 1][0], sc[2 * kb + 1][1], ah2, al2);
            pack_hl(sc[2 * kb + 1][2], sc[2 * kb + 1][3], ah3, al3);
#pragma unroll
            for (int jp = 0; jp < 4; jp++) {
                uint32_t brow = 16 * jp + ((mmi >> 1) << 3) + rr;
                uint32_t bbyte = kb * 32 + ((mmi & 1) << 4);
                uint32_t boff = swzb_u(brow, bbyte);
                uint32_t bh0, bh1, bh2, bh3, bl0, bl1, bl2, bl3;
                ldsm_x4(bh0, bh1, bh2, bh3, uVh + boff);
                ldsm_x4(bl0, bl1, bl2, bl3, uVl + boff);
                mma16816(oacc[2 * jp], ah0, ah1, ah2, ah3, bh0, bh1);
                mma16816(oacc[2 * jp], ah0, ah1, ah2, ah3, bl0, bl1);
                mma16816(oacc[2 * jp], al0, al1, al2, al3, bh0, bh1);
                mma16816(oacc[2 * jp + 1], ah0, ah1, ah2, ah3, bh2, bh3);
                mma16816(oacc[2 * jp + 1], ah0, ah1, ah2, ah3, bl2, bl3);
                mma16816(oacc[2 * jp + 1], al0, al1, al2, al3, bh2, bh3);
            }
        }
        __syncthreads();   // done reading cur buffer before next overwrite
    }

    // Epilogue: normalize + write bf16 hi/lo
    float inv0 = 1.f / rsum0;
    float inv1 = 1.f / rsum1;
    size_t base0 = ((size_t)b * S_ + q0 + 16 * w + g) * H_ + n * HD_;
    size_t base1 = base0 + 8 * H_;
#pragma unroll
    for (int j = 0; j < 8; j++) {
        int col = 8 * j + 2 * t4;
        uint32_t h0, l0, h1, l1;
        pack_hl(oacc[j][0] * inv0, oacc[j][1] * inv0, h0, l0);
        pack_hl(oacc[j][2] * inv1, oacc[j][3] * inv1, h1, l1);
        *(uint32_t*)(Aout_h + base0 + col) = h0;
        *(uint32_t*)(Aout_l + base0 + col) = l0;
        *(uint32_t*)(Aout_h + base1 + col) = h1;
        *(uint32_t*)(Aout_l + base1 + col) = l1;
    }
}

// ---------------------------------------------------------------------------
// Launch
// ---------------------------------------------------------------------------
extern "C" void kernel_launch(void* const* d_in, const int* in_sizes, int n_in,
                              void* d_out, int out_size)
{
    const float* x   = (const float*)d_in[0];
    const float* Wq  = (const float*)d_in[1];
    const float* bq  = (const float*)d_in[2];
    const float* Wk  = (const float*)d_in[3];
    const float* bk  = (const float*)d_in[4];
    const float* Wv  = (const float*)d_in[5];
    const float* bv  = (const float*)d_in[6];
    const float* Wo  = (const float*)d_in[7];
    const float* bo  = (const float*)d_in[8];
    const float* rel = (const float*)d_in[9];
    float* out = (float*)d_out;

    float* pV;
    __nv_bfloat16 *xh, *xl, *wqh, *wql, *wkh, *wkl, *wvh, *wvl, *woh, *wol, *ah, *al;
    __nv_bfloat16 *qh, *ql, *kh, *kl, *vth, *vtl, *relB;
    cudaGetSymbolAddress((void**)&pV, g_V);
    cudaGetSymbolAddress((void**)&xh, g_xh);
    cudaGetSymbolAddress((void**)&xl, g_xl);
    cudaGetSymbolAddress((void**)&wqh, g_Wqh);
    cudaGetSymbolAddress((void**)&wql, g_Wql);
    cudaGetSymbolAddress((void**)&wkh, g_Wkh);
    cudaGetSymbolAddress((void**)&wkl, g_Wkl);
    cudaGetSymbolAddress((void**)&wvh, g_Wvh);
    cudaGetSymbolAddress((void**)&wvl, g_Wvl);
    cudaGetSymbolAddress((void**)&woh, g_Woh);
    cudaGetSymbolAddress((void**)&wol, g_Wol);
    cudaGetSymbolAddress((void**)&ah, g_ah);
    cudaGetSymbolAddress((void**)&al, g_al);
    cudaGetSymbolAddress((void**)&qh, g_Qh);
    cudaGetSymbolAddress((void**)&ql, g_Ql);
    cudaGetSymbolAddress((void**)&kh, g_Kh);
    cudaGetSymbolAddress((void**)&kl, g_Kl);
    cudaGetSymbolAddress((void**)&vth, g_Vth);
    cudaGetSymbolAddress((void**)&vtl, g_Vtl);
    cudaGetSymbolAddress((void**)&relB, g_relB);

    cudaFuncSetAttribute(attn_mma, cudaFuncAttributeMaxDynamicSharedMemorySize, ATTN_SMEM);
    cudaFuncSetAttribute(gemm_mma, cudaFuncAttributeMaxDynamicSharedMemorySize, GEMM_SMEM);
    cudaFuncSetAttribute(gemm_qkv, cudaFuncAttributeMaxDynamicSharedMemorySize, GEMM_SMEM);

    split_all<<<SPLIT_BLOCKS, 256>>>(
        (const float4*)x,  (uint2*)xh,  (uint2*)xl,
        (const float4*)Wq, (uint2*)wqh, (uint2*)wql,
        (const float4*)Wk, (uint2*)wkh, (uint2*)wkl,
        (const float4*)Wv, (uint2*)wvh, (uint2*)wvl,
        (const float4*)Wo, (uint2*)woh, (uint2*)wol,
        (const float4*)rel, (uint2*)relB);

    dim3 qkv_grid(H_ / 128, MTOT / 128, 3);   // (8, 32, 3) = 768 blocks
    gemm_qkv<<<qkv_grid, 256, GEMM_SMEM>>>(xh, xl,
        wqh, wql, bq, qh, ql,
        wkh, wkl, bk, kh, kl,
        wvh, wvl, bv, pV);

    vtrans_kernel<<<dim3(S_ / 64, NH_, B_), 256>>>(pV, vth, vtl);

    dim3 attn_grid(S_ / 64, NH_, B_);
    attn_mma<<<attn_grid, 128, ATTN_SMEM>>>(qh, ql, kh, kl, vth, vtl, relB, ah, al);

    dim3 gemm_grid(H_ / 128, MTOT / 128);
    gemm_mma<<<gemm_grid, 256, GEMM_SMEM>>>(ah, al, woh, wol, bo, out);
}